// round 17
// baseline (speedup 1.0000x reference)
#include <cuda_runtime.h>
#include <math.h>

#define BB 256
#define SS 4096
#define HH 64
#define GG 192   // 3*H
#define TS 128   // attn tile steps
#define NH2 2    // sequence splits per batch

// Scratch: layer activations, in-place across layers, per-batch contiguous.
__device__ float g_buf[(size_t)BB * SS * HH];      // 268 MB
// attn partials: [b][half][head] scalars, [b][half][head][e] vectors
__device__ float g_pm[BB * NH2 * 4];
__device__ float g_pl[BB * NH2 * 4];
__device__ float g_pu[BB * NH2 * 4 * HH];

__device__ __forceinline__ float sigmoidf_(float x) {
    return 1.0f / (1.0f + __expf(-x));
}
__device__ __forceinline__ float tanhf_(float x) {
    x = fminf(fmaxf(x, -15.0f), 15.0f);
    float e = __expf(2.0f * x);
    return (e - 1.0f) / (e + 1.0f);
}

// ---------------------------------------------------------------------------
// GRU layer — EXACT R1 structure (frozen; measured best).
// ---------------------------------------------------------------------------
template <bool FIRST>
__device__ void gru_layer(
    const float* __restrict__ wih, const float* __restrict__ whh,
    const float* __restrict__ bih, const float* __restrict__ bhh,
    const float* __restrict__ inp,
    float* __restrict__ outp,
    float* sh, float (*sx)[HH], float* srz)
{
    const int j = threadIdx.x;
    constexpr int IN = FIRST ? 1 : HH;

    float wi[IN];
    float wh[HH];
#pragma unroll
    for (int k = 0; k < HH; k++) wh[k] = whh[j * HH + k];
#pragma unroll
    for (int k = 0; k < IN; k++) wi[k] = wih[j * IN + k];
    const float bi = bih[j];
    const float bh = bhh[j];

    if (j < HH) sh[j] = 0.0f;
    float xreg = 0.0f;
    if (j < IN) {
        sx[0][j] = inp[j];
        xreg     = inp[(size_t)IN + j];
    }
    __syncthreads();

    for (int t = 0; t < SS; t++) {
        const int cur = t & 1;
        float ai;
        if (FIRST) {
            ai = fmaf(wi[0], sx[cur][0], bi);
        } else {
            const float4* xv = (const float4*)sx[cur];
            float a0 = bi, a1 = 0.f, a2 = 0.f, a3 = 0.f;
#pragma unroll
            for (int kk = 0; kk < 16; kk++) {
                float4 v = xv[kk];
                a0 = fmaf(wi[4 * kk + 0], v.x, a0);
                a1 = fmaf(wi[4 * kk + 1], v.y, a1);
                a2 = fmaf(wi[4 * kk + 2], v.z, a2);
                a3 = fmaf(wi[4 * kk + 3], v.w, a3);
            }
            ai = (a0 + a1) + (a2 + a3);
        }
        float ah;
        {
            const float4* hv = (const float4*)sh;
            float a0 = bh, a1 = 0.f, a2 = 0.f, a3 = 0.f;
#pragma unroll
            for (int kk = 0; kk < 16; kk++) {
                float4 v = hv[kk];
                a0 = fmaf(wh[4 * kk + 0], v.x, a0);
                a1 = fmaf(wh[4 * kk + 1], v.y, a1);
                a2 = fmaf(wh[4 * kk + 2], v.z, a2);
                a3 = fmaf(wh[4 * kk + 3], v.w, a3);
            }
            ah = (a0 + a1) + (a2 + a3);
        }
        if (j < 128) srz[j] = sigmoidf_(ai + ah);
        __syncthreads();

        if (j >= 128) {
            const int k = j - 128;
            float r = srz[k];
            float z = srz[64 + k];
            float n = tanhf_(fmaf(r, ah, ai));
            float hp = sh[k];
            float hn = fmaf(z, hp - n, n);
            sh[k] = hn;
            outp[(size_t)t * HH + k] = hn;
        } else if (j < IN) {
            sx[1 - cur][j] = xreg;
            xreg = (t + 2 < SS) ? inp[(size_t)(t + 2) * IN + j] : 0.0f;
        }
        __syncthreads();
    }
}

__global__ __launch_bounds__(GG)
void gru_kernel(
    const float* __restrict__ x,
    const float* __restrict__ wih0, const float* __restrict__ whh0,
    const float* __restrict__ bih0, const float* __restrict__ bhh0,
    const float* __restrict__ wih1, const float* __restrict__ whh1,
    const float* __restrict__ bih1, const float* __restrict__ bhh1,
    const float* __restrict__ wih2, const float* __restrict__ whh2,
    const float* __restrict__ bih2, const float* __restrict__ bhh2)
{
    __shared__ __align__(16) float sh[HH];
    __shared__ __align__(16) float sx[2][HH];
    __shared__ float srz[128];

    const int b = blockIdx.x;
    float* buf = g_buf + (size_t)b * SS * HH;

    gru_layer<true >(wih0, whh0, bih0, bhh0, x + (size_t)b * SS, buf, sh, sx, srz);
    __syncthreads();
    gru_layer<false>(wih1, whh1, bih1, bhh1, buf, buf, sh, sx, srz);
    __syncthreads();
    gru_layer<false>(wih2, whh2, bih2, bhh2, buf, buf, sh, sx, srz);
}

// ---------------------------------------------------------------------------
// attn part: one CTA per (batch, sequence-half). Computes partial online
// softmax over its 2048 steps (16 tiles of TS=128): running max m, partial
// sum l, unnormalized weighted sum u (all relative to this half's m).
// Same verified tile math as R16's fused kernel.
// ---------------------------------------------------------------------------
__global__ __launch_bounds__(256)
void attn_part_kernel(
    const float* __restrict__ in_proj_w, const float* __restrict__ in_proj_b)
{
    const int b2 = blockIdx.x;
    const int b = b2 >> 1;
    const int half = b2 & 1;
    const int tid = threadIdx.x;
    const int h = tid >> 6;
    const int e = tid & 63;

    __shared__ __align__(16) float shl[HH];
    __shared__ __align__(16) float sq[HH];
    __shared__ __align__(16) float sg[4][HH];
    __shared__ float sc[4];
    __shared__ float stile[TS][65];
    __shared__ float swv[4][TS];
    __shared__ float swm[4][2];
    __shared__ float sm_run[4];
    __shared__ float sscale[4];
    __shared__ float sred[256];

    const float* mybuf = g_buf + (size_t)b * SS * HH;

    // ---- q = Wq h_last + bq; fold Wk -> g, c ----
    if (tid < HH) shl[tid] = mybuf[(size_t)(SS - 1) * HH + tid];
    __syncthreads();
    if (tid < HH) {
        float acc = in_proj_b[tid];
#pragma unroll
        for (int k = 0; k < HH; k++)
            acc = fmaf(in_proj_w[tid * HH + k], shl[k], acc);
        sq[tid] = acc;
    }
    __syncthreads();
    if (tid < HH) {
#pragma unroll
        for (int hh = 0; hh < 4; hh++) {
            float acc = 0.0f;
#pragma unroll
            for (int d = 0; d < 16; d++)
                acc = fmaf(sq[hh * 16 + d], in_proj_w[(HH + hh * 16 + d) * HH + tid], acc);
            sg[hh][tid] = acc * 0.25f;
        }
    }
    if (tid < 4) {
        float acc = 0.0f;
#pragma unroll
        for (int d = 0; d < 16; d++)
            acc = fmaf(sq[tid * 16 + d], in_proj_b[HH + tid * 16 + d], acc);
        sc[tid] = acc * 0.25f;
        sm_run[tid] = -1e30f;
    }
    __syncthreads();

    float uacc = 0.0f;
    float lloc = 0.0f;
    const int tile0 = half * (SS / TS / NH2);          // 0 or 16
    const int tile1 = tile0 + SS / TS / NH2;

    for (int tile = tile0; tile < tile1; tile++) {
        const int s0 = tile * TS;
        {
            const float4* gv = (const float4*)(mybuf + (size_t)s0 * HH);
#pragma unroll
            for (int r = 0; r < (TS * HH / 4) / 256; r++) {
                int idx = tid + r * 256;
                int row = idx >> 4, c4 = (idx & 15) * 4;
                float4 v = gv[idx];
                stile[row][c4 + 0] = v.x;
                stile[row][c4 + 1] = v.y;
                stile[row][c4 + 2] = v.z;
                stile[row][c4 + 3] = v.w;
            }
        }
        __syncthreads();

        float s0v, s1v;
#pragma unroll
        for (int hf = 0; hf < 2; hf++) {
            const int sp = e + hf * 64;
            float a0 = sc[h], a1 = 0.f, a2 = 0.f, a3 = 0.f;
#pragma unroll
            for (int k = 0; k < HH; k += 4) {
                a0 = fmaf(sg[h][k + 0], stile[sp][k + 0], a0);
                a1 = fmaf(sg[h][k + 1], stile[sp][k + 1], a1);
                a2 = fmaf(sg[h][k + 2], stile[sp][k + 2], a2);
                a3 = fmaf(sg[h][k + 3], stile[sp][k + 3], a3);
            }
            float sv = (a0 + a1) + (a2 + a3);
            swv[h][sp] = sv;
            if (hf == 0) s0v = sv; else s1v = sv;
        }

        float wm = fmaxf(s0v, s1v);
#pragma unroll
        for (int off = 16; off > 0; off >>= 1)
            wm = fmaxf(wm, __shfl_xor_sync(0xFFFFFFFFu, wm, off));
        if ((tid & 31) == 0) swm[h][(tid >> 5) & 1] = wm;
        __syncthreads();

        if (tid < 4) {
            float mt = fmaxf(swm[tid][0], swm[tid][1]);
            float mo = sm_run[tid];
            float mn = fmaxf(mo, mt);
            sscale[tid] = __expf(mo - mn);
            sm_run[tid] = mn;
        }
        __syncthreads();

        const float scl = sscale[h];
        const float mh = sm_run[h];
        float w0 = __expf(swv[h][e] - mh);
        float w1 = __expf(swv[h][e + 64] - mh);
        swv[h][e] = w0;
        swv[h][e + 64] = w1;
        lloc = fmaf(lloc, scl, w0 + w1);
        __syncthreads();

        {
            float acc = 0.0f;
#pragma unroll
            for (int sp = 0; sp < TS; sp++)
                acc = fmaf(swv[h][sp], stile[sp][e], acc);
            uacc = fmaf(uacc, scl, acc);
        }
        __syncthreads();
    }

    // ---- write partials ----
    sred[tid] = lloc;
    __syncthreads();
    if (tid < 4) {
        float l = 0.0f;
        for (int i = 0; i < 64; i++) l += sred[tid * 64 + i];
        g_pl[b2 * 4 + tid] = l;
        g_pm[b2 * 4 + tid] = sm_run[tid];
    }
    g_pu[(size_t)(b2 * 4 + h) * HH + e] = uacc;
}

// ---------------------------------------------------------------------------
// attn final: combine the two halves' partials (flash rescale), then
// ctx = Wv u + bv, out_proj, fc, sigmoid. One CTA per batch, 256 threads.
// ---------------------------------------------------------------------------
__global__ __launch_bounds__(256)
void attn_final_kernel(
    const float* __restrict__ in_proj_w, const float* __restrict__ in_proj_b,
    const float* __restrict__ out_proj_w, const float* __restrict__ out_proj_b,
    const float* __restrict__ fc_w, const float* __restrict__ fc_b,
    float* __restrict__ out)
{
    const int b = blockIdx.x;
    const int tid = threadIdx.x;
    const int h = tid >> 6;
    const int e = tid & 63;

    __shared__ float sscl[2][4], sl4[4];
    __shared__ float su[4][HH];
    __shared__ __align__(16) float sctx[HH];
    __shared__ float sao[HH];

    const int p0 = (b * 2) * 4, p1 = (b * 2 + 1) * 4;

    if (tid < 4) {
        float m0 = g_pm[p0 + tid], m1 = g_pm[p1 + tid];
        float m = fmaxf(m0, m1);
        float c0 = __expf(m0 - m), c1 = __expf(m1 - m);
        sscl[0][tid] = c0;
        sscl[1][tid] = c1;
        sl4[tid] = g_pl[p0 + tid] * c0 + g_pl[p1 + tid] * c1;
    }
    __syncthreads();

    {
        float u0 = g_pu[(size_t)(p0 + h) * HH + e];
        float u1 = g_pu[(size_t)(p1 + h) * HH + e];
        su[h][e] = (u0 * sscl[0][h] + u1 * sscl[1][h]) / sl4[h];
    }
    __syncthreads();

    if (tid < HH) {
        const int hh = tid >> 4;
        float acc = in_proj_b[128 + tid];
#pragma unroll
        for (int k = 0; k < HH; k++)
            acc = fmaf(in_proj_w[(128 + tid) * HH + k], su[hh][k], acc);
        sctx[tid] = acc;
    }
    __syncthreads();

    if (tid < HH) {
        float acc = out_proj_b[tid];
#pragma unroll
        for (int k = 0; k < HH; k++)
            acc = fmaf(out_proj_w[tid * HH + k], sctx[k], acc);
        sao[tid] = fc_w[tid] * acc;
    }
    __syncthreads();

    if (tid == 0) {
        float lg = fc_b[0];
        for (int i = 0; i < HH; i++) lg += sao[i];
        out[b] = 1.0f / (1.0f + __expf(-lg));
    }
}

// ---------------------------------------------------------------------------
extern "C" void kernel_launch(void* const* d_in, const int* in_sizes, int n_in,
                              void* d_out, int out_size)
{
    const float* x    = (const float*)d_in[0];
    const float* wih0 = (const float*)d_in[1];
    const float* whh0 = (const float*)d_in[2];
    const float* bih0 = (const float*)d_in[3];
    const float* bhh0 = (const float*)d_in[4];
    const float* wih1 = (const float*)d_in[5];
    const float* whh1 = (const float*)d_in[6];
    const float* bih1 = (const float*)d_in[7];
    const float* bhh1 = (const float*)d_in[8];
    const float* wih2 = (const float*)d_in[9];
    const float* whh2 = (const float*)d_in[10];
    const float* bih2 = (const float*)d_in[11];
    const float* bhh2 = (const float*)d_in[12];
    const float* ipw  = (const float*)d_in[13];
    const float* ipb  = (const float*)d_in[14];
    const float* opw  = (const float*)d_in[15];
    const float* opb  = (const float*)d_in[16];
    const float* fcw  = (const float*)d_in[17];
    const float* fcb  = (const float*)d_in[18];

    gru_kernel<<<BB, GG>>>(x, wih0, whh0, bih0, bhh0,
                           wih1, whh1, bih1, bhh1,
                           wih2, whh2, bih2, bhh2);
    attn_part_kernel<<<BB * NH2, 256>>>(ipw, ipb);
    attn_final_kernel<<<BB, 256>>>(ipw, ipb, opw, opb, fcw, fcb, (float*)d_out);
}